// round 1
// baseline (speedup 1.0000x reference)
#include <cuda_runtime.h>
#include <cstdint>

typedef unsigned long long ull;

// Binarized weights, layout [ci][tap][co] (co contiguous), tap = kh*3+kw.
__device__ __align__(16) float g_wbin[576 * 64];

__device__ __forceinline__ ull f2x2(float lo, float hi) {
    ull r;
    asm("mov.b64 %0, {%1, %2};" : "=l"(r) : "f"(lo), "f"(hi));
    return r;
}

// Packed dual-FP32 FMA (Blackwell). Elementwise identical to two FFMAs.
__device__ __forceinline__ ull ffma2(ull a, ull b, ull c) {
    ull d;
    asm("fma.rn.f32x2 %0, %1, %2, %3;" : "=l"(d) : "l"(a), "l"(b), "l"(c));
    return d;
}

// ---------------------------------------------------------------------------
// Kernel 1: binarize weights. One block per output channel, 576 threads
// (one per weight element of that channel).
// bw = sign(w - mean) * exp2(rint(log2( mean|w-mean| / std )))
// with std = sqrt(sum((w-mean)^2)/575)  (ddof=1), mean over 576 elems.
// ---------------------------------------------------------------------------
__global__ void binarize_kernel(const float* __restrict__ w) {
    __shared__ float rb[18], rb2[18], rb3[18];
    __shared__ float s_mean, s_scale;

    const int co = blockIdx.x;
    const int e = threadIdx.x;          // 0..575 : e = ci*9 + tap
    const int lane = e & 31, wid = e >> 5;

    const float v = w[co * 576 + e];

    // mean
    float s = v;
    #pragma unroll
    for (int o = 16; o > 0; o >>= 1) s += __shfl_down_sync(0xffffffffu, s, o);
    if (lane == 0) rb[wid] = s;
    __syncthreads();
    if (e == 0) {
        float t = 0.f;
        for (int i = 0; i < 18; ++i) t += rb[i];
        s_mean = t * (1.0f / 576.0f);
    }
    __syncthreads();

    const float d = v - s_mean;
    float sq = d * d;
    float ab = fabsf(d);
    #pragma unroll
    for (int o = 16; o > 0; o >>= 1) {
        sq += __shfl_down_sync(0xffffffffu, sq, o);
        ab += __shfl_down_sync(0xffffffffu, ab, o);
    }
    if (lane == 0) { rb2[wid] = sq; rb3[wid] = ab; }
    __syncthreads();
    if (e == 0) {
        float t2 = 0.f, t3 = 0.f;
        for (int i = 0; i < 18; ++i) { t2 += rb2[i]; t3 += rb3[i]; }
        const float stdv = sqrtf(t2 / 575.0f);
        const float mean_abs = t3 / (576.0f * stdv);
        s_scale = exp2f(rintf(log2f(mean_abs)));   // rint = round-half-even, matches jnp.round
    }
    __syncthreads();

    const float sw = s_scale;
    const float bv = (d > 0.f) ? sw : ((d < 0.f) ? -sw : 0.f);
    g_wbin[e * 64 + co] = bv;
}

// ---------------------------------------------------------------------------
// Kernel 2: fused conv3x3(pad1) + per-channel LUT bucketize.
// Block: 256 threads -> output tile of 64 co x 16 rows x 16 cols (one image).
// Warp wp handles co in [8*wp, 8*wp+8); lane l handles row l/2, col group (l&1)*8.
// Each thread accumulates 8co x 8px as 4 co-pairs x 8 px packed f32x2.
// Input channels staged through smem in 16 chunks of 4.
// ---------------------------------------------------------------------------
__global__ void __launch_bounds__(256, 2)
conv_lut_kernel(const float* __restrict__ x,
                const float* __restrict__ lut,
                float* __restrict__ out) {
    __shared__ __align__(16) float sx[4][18][18];     // [ci][row(+halo)][col(+halo)]
    __shared__ __align__(16) float swp[4 * 9 * 64];   // [ci][tap][co]
    __shared__ float slut[64 * 7];

    const int n  = blockIdx.z;
    const int bx = blockIdx.x;   // col tile (16 wide), 7 tiles
    const int by = blockIdx.y;   // row tile (16 tall), 7 tiles
    const int tid = threadIdx.x;
    const int wp  = tid >> 5;
    const int l   = tid & 31;
    const int lrow = l >> 1;           // 0..15
    const int colg = (l & 1) << 3;     // 0 or 8
    const int co0  = wp << 3;          // 0,8,...,56

    for (int i = tid; i < 448; i += 256) slut[i] = lut[i];

    ull acc[4][8];
    #pragma unroll
    for (int a = 0; a < 4; ++a)
        #pragma unroll
        for (int j = 0; j < 8; ++j) acc[a][j] = 0ull;

    const float* xin = x + (size_t)n * 64 * 12544;

    for (int cc = 0; cc < 16; ++cc) {
        const int c0 = cc * 4;
        __syncthreads();

        // Stage x chunk: 4 ci x 18x18 (with halo, zero-padded at borders)
        for (int i = tid; i < 4 * 18 * 18; i += 256) {
            const int ci  = i / 324;
            const int rem = i - ci * 324;
            const int r   = rem / 18;
            const int c   = rem - r * 18;
            const int gr  = by * 16 + r - 1;
            const int gc  = bx * 16 + c - 1;
            float v = 0.f;
            if ((unsigned)gr < 112u && (unsigned)gc < 112u)
                v = xin[(size_t)(c0 + ci) * 12544 + gr * 112 + gc];
            sx[ci][r][c] = v;
        }
        // Stage w chunk: 4 ci x 9 taps x 64 co (contiguous in g_wbin)
        {
            const float4* src = reinterpret_cast<const float4*>(g_wbin + c0 * 576);
            float4* dst = reinterpret_cast<float4*>(swp);
            for (int i = tid; i < 576; i += 256) dst[i] = src[i];
        }
        __syncthreads();

        #pragma unroll
        for (int cil = 0; cil < 4; ++cil) {
            #pragma unroll
            for (int kh = 0; kh < 3; ++kh) {
                // x window for this (ci,kh): 10 consecutive values starting at colg
                const float2* xp =
                    reinterpret_cast<const float2*>(&sx[cil][lrow + kh][colg]);
                const float2 xv0 = xp[0], xv1 = xp[1], xv2 = xp[2],
                             xv3 = xp[3], xv4 = xp[4];
                ull xs[10];
                xs[0] = f2x2(xv0.x, xv0.x); xs[1] = f2x2(xv0.y, xv0.y);
                xs[2] = f2x2(xv1.x, xv1.x); xs[3] = f2x2(xv1.y, xv1.y);
                xs[4] = f2x2(xv2.x, xv2.x); xs[5] = f2x2(xv2.y, xv2.y);
                xs[6] = f2x2(xv3.x, xv3.x); xs[7] = f2x2(xv3.y, xv3.y);
                xs[8] = f2x2(xv4.x, xv4.x); xs[9] = f2x2(xv4.y, xv4.y);

                #pragma unroll
                for (int kw = 0; kw < 3; ++kw) {
                    // 8 co weights = 4 packed co-pairs (lo lane = even co)
                    const ulonglong2* w2 = reinterpret_cast<const ulonglong2*>(
                        &swp[((cil * 9 + kh * 3 + kw) << 6) + co0]);
                    const ulonglong2 wa = w2[0], wb = w2[1];
                    #pragma unroll
                    for (int j = 0; j < 8; ++j) {
                        acc[0][j] = ffma2(wa.x, xs[kw + j], acc[0][j]);
                        acc[1][j] = ffma2(wa.y, xs[kw + j], acc[1][j]);
                        acc[2][j] = ffma2(wb.x, xs[kw + j], acc[2][j]);
                        acc[3][j] = ffma2(wb.y, xs[kw + j], acc[3][j]);
                    }
                }
            }
        }
    }

    // Epilogue: LUT bucketize (faithful threshold chain, last match wins) + store
    const int gr  = by * 16 + lrow;
    const int gc  = bx * 16 + colg;
    float* outn = out + (size_t)n * 64 * 12544;

    #pragma unroll
    for (int cp = 0; cp < 4; ++cp) {
        #pragma unroll
        for (int h = 0; h < 2; ++h) {
            const int co = co0 + cp * 2 + h;
            const float* tt = &slut[co * 7];
            const float t0 = tt[0], t1 = tt[1], t2 = tt[2], t3 = tt[3],
                        t4 = tt[4], t5 = tt[5], t6 = tt[6];
            float* orow = outn + (size_t)co * 12544 + gr * 112 + gc;
            #pragma unroll
            for (int j = 0; j < 8; ++j) {
                union { ull u; float f[2]; } cv;
                cv.u = acc[cp][j];
                const float v = cv.f[h];
                float r = v;
                if (v <= t0)            r = 0.f;
                if (v > t0 && v < t1)   r = 1.f;
                if (v >= t1 && v <= t2) r = 2.f;
                if (v > t2 && v < t3)   r = 3.f;
                if (v >= t3 && v <= t4) r = 4.f;
                if (v > t4 && v < t5)   r = 5.f;
                if (v >= t5 && v <= t6) r = 6.f;
                if (v > t6)             r = 7.f;
                orow[j] = r;
            }
        }
    }
}

// ---------------------------------------------------------------------------
extern "C" void kernel_launch(void* const* d_in, const int* in_sizes, int n_in,
                              void* d_out, int out_size) {
    (void)in_sizes; (void)n_in; (void)out_size;
    const float* x   = (const float*)d_in[0];   // [32,64,112,112]
    const float* w   = (const float*)d_in[1];   // [64,64,3,3]
    const float* lut = (const float*)d_in[2];   // [64,7]
    float* out = (float*)d_out;                 // [32,64,112,112]

    binarize_kernel<<<64, 576>>>(w);
    conv_lut_kernel<<<dim3(7, 7, 32), 256>>>(x, lut, out);
}

// round 3
// speedup vs baseline: 2.8045x; 2.8045x over previous
#include <cuda_runtime.h>
#include <cuda_bf16.h>
#include <cstdint>

typedef unsigned long long ull;
typedef uint32_t u32;

#define ROWS_IMG 12996          // 114*114 padded pixels per image
#define GUARD    128
#define TOT_ROWS (GUARD + 32 * ROWS_IMG + 256)

// scratch: [row][128 bf16] = 256 B/row : split0 (64 ci bf16) | split1 (64 ci bf16)
__device__ __align__(16) __nv_bfloat16 g_scratch[(size_t)TOT_ROWS * 128];
__device__ __align__(16) __nv_bfloat16 g_wbf[9 * 64 * 64];   // [tap][co][ci]

// ---------------- helpers ----------------
__device__ __forceinline__ u32 smem_u32(const void* p) {
    u32 a;
    asm("{ .reg .u64 t; cvta.to.shared.u64 t, %1; cvt.u32.u64 %0, t; }" : "=r"(a) : "l"(p));
    return a;
}
__device__ __forceinline__ void cp16(u32 dst, const void* src) {
    asm volatile("cp.async.cg.shared.global [%0], [%1], 16;" :: "r"(dst), "l"(src));
}
#define CP_COMMIT() asm volatile("cp.async.commit_group;" ::: "memory")

__device__ __forceinline__ void ldm4(u32* r, u32 addr) {
    asm volatile("ldmatrix.sync.aligned.m8n8.x4.shared.b16 {%0,%1,%2,%3}, [%4];"
                 : "=r"(r[0]), "=r"(r[1]), "=r"(r[2]), "=r"(r[3]) : "r"(addr));
}
__device__ __forceinline__ void mma16816(float* c, const u32* a, u32 b0, u32 b1) {
    asm volatile(
        "mma.sync.aligned.m16n8k16.row.col.f32.bf16.bf16.f32 "
        "{%0,%1,%2,%3}, {%4,%5,%6,%7}, {%8,%9}, {%0,%1,%2,%3};"
        : "+f"(c[0]), "+f"(c[1]), "+f"(c[2]), "+f"(c[3])
        : "r"(a[0]), "r"(a[1]), "r"(a[2]), "r"(a[3]), "r"(b0), "r"(b1));
}

// ---------------------------------------------------------------------------
// Kernel 1: binarize weights -> bf16, layout [tap][co][ci]
// ---------------------------------------------------------------------------
__global__ void binarize_kernel(const float* __restrict__ w) {
    __shared__ float rb[18], rb2[18], rb3[18];
    __shared__ float s_mean, s_scale;
    const int co = blockIdx.x;
    const int e = threadIdx.x;           // e = ci*9 + tap
    const int lane = e & 31, wid = e >> 5;
    const float v = w[co * 576 + e];

    float s = v;
    #pragma unroll
    for (int o = 16; o > 0; o >>= 1) s += __shfl_down_sync(0xffffffffu, s, o);
    if (lane == 0) rb[wid] = s;
    __syncthreads();
    if (e == 0) {
        float t = 0.f;
        for (int i = 0; i < 18; ++i) t += rb[i];
        s_mean = t * (1.0f / 576.0f);
    }
    __syncthreads();
    const float d = v - s_mean;
    float sq = d * d, ab = fabsf(d);
    #pragma unroll
    for (int o = 16; o > 0; o >>= 1) {
        sq += __shfl_down_sync(0xffffffffu, sq, o);
        ab += __shfl_down_sync(0xffffffffu, ab, o);
    }
    if (lane == 0) { rb2[wid] = sq; rb3[wid] = ab; }
    __syncthreads();
    if (e == 0) {
        float t2 = 0.f, t3 = 0.f;
        for (int i = 0; i < 18; ++i) { t2 += rb2[i]; t3 += rb3[i]; }
        const float stdv = sqrtf(t2 / 575.0f);
        const float mean_abs = t3 / (576.0f * stdv);
        s_scale = exp2f(rintf(log2f(mean_abs)));
    }
    __syncthreads();
    const float bv = (d > 0.f) ? s_scale : ((d < 0.f) ? -s_scale : 0.f);
    const int tap = e % 9, ci = e / 9;
    g_wbf[(tap * 64 + co) * 64 + ci] = __float2bfloat16(bv);
}

// ---------------------------------------------------------------------------
// Kernel 2: zero padding regions of scratch
// ---------------------------------------------------------------------------
__global__ void pad_zero_kernel() {
    const int n = blockIdx.x;
    uint4* base = reinterpret_cast<uint4*>(g_scratch);   // 16 uint4 per row
    const size_t imgrow0 = GUARD + (size_t)n * ROWS_IMG;
    const uint4 z = make_uint4(0, 0, 0, 0);
    // padded rows r'=0 (img row -1) and r'=113 (img row 112): 114 rows each
    for (int i = threadIdx.x; i < 228 * 16; i += blockDim.x) {
        const int r = i >> 4, c = i & 15;
        const size_t row = imgrow0 + (r < 114 ? r : (12882 - 114 + r));
        base[row * 16 + c] = z;
    }
    // pad cols 112,113 for padded rows r'=1..112
    for (int i = threadIdx.x; i < 112 * 2 * 16; i += blockDim.x) {
        const int rp  = 1 + (i >> 5);
        const int col = 112 + ((i >> 4) & 1);
        const int c   = i & 15;
        base[(imgrow0 + (size_t)rp * 114 + col) * 16 + c] = z;
    }
    if (n == 0) {
        for (int i = threadIdx.x; i < GUARD * 16; i += blockDim.x) base[i] = z;
    }
}

// ---------------------------------------------------------------------------
// Kernel 3: convert x fp32 [n][ci][q] -> bf16 2-split scratch rows
// ---------------------------------------------------------------------------
__global__ void convert_kernel(const float* __restrict__ x) {
    __shared__ float sm[64][33];
    const int n = blockIdx.y;
    const int q0 = blockIdx.x * 32;
    const int t = threadIdx.x;
    const int w8 = t >> 5, l = t & 31;
    #pragma unroll
    for (int r = 0; r < 8; ++r) {
        const int ci = w8 * 8 + r;
        sm[ci][l] = x[((size_t)n * 64 + ci) * 12544 + q0 + l];
    }
    __syncthreads();
    const int pix = t >> 3, g = t & 7;
    const int q = q0 + pix;
    const int r = q / 112, c = q - r * 112;
    const size_t row = GUARD + (size_t)n * ROWS_IMG + (size_t)(r + 1) * 114 + c;
    __nv_bfloat16* dst = g_scratch + row * 128 + g * 8;
    __nv_bfloat16 hi[8], lo[8];
    #pragma unroll
    for (int i = 0; i < 8; ++i) {
        const float f = sm[g * 8 + i][pix];
        hi[i] = __float2bfloat16(f);
        const float r1 = f - __bfloat162float(hi[i]);
        lo[i] = __float2bfloat16(r1);
    }
    *reinterpret_cast<uint4*>(dst)      = *reinterpret_cast<uint4*>(hi);
    *reinterpret_cast<uint4*>(dst + 64) = *reinterpret_cast<uint4*>(lo);
}

// ---------------------------------------------------------------------------
// Kernel 4: implicit-GEMM conv via mma.sync m16n8k16 bf16 + LUT bucketize
// ---------------------------------------------------------------------------
#define APITCH 272
#define A_OFF  0
#define B_OFF  97408                    // 358*272 = 97376, padded
#define BPITCH 144
#define BTAP   (64 * 144)               // 9216
#define LUT_OFF (B_OFF + 9 * BTAP)      // 180352
#define SMEM_TOTAL (LUT_OFF + 1792 + 64)

__global__ void __launch_bounds__(128, 1)
conv_mma_kernel(const float* __restrict__ lut, float* __restrict__ out) {
    extern __shared__ __align__(1024) char smem[];
    const u32 sb = smem_u32(smem);
    const int tid = threadIdx.x, warp = tid >> 5, lane = tid & 31;
    const int tile = blockIdx.x, n = blockIdx.y;
    const int s0 = 114 + tile * 128;
    const size_t imgrow0 = GUARD + (size_t)n * ROWS_IMG;
    const long g0 = (long)s0 - 115;     // first staged global (image-local) row

    // ---- stage B (9 taps, 64co x 64ci -> 144B pitch, conflict-free) ----
    {
        const char* wsrc = reinterpret_cast<const char*>(g_wbf);
        for (int i = tid; i < 9 * 64 * 8; i += 128) {
            const int tap = i >> 9, r = (i >> 3) & 63, c = i & 7;
            cp16(sb + B_OFF + tap * BTAP + r * BPITCH + c * 16,
                 wsrc + ((size_t)(tap * 64 + r) * 64 + c * 8) * 2);
        }
    }
    for (int i = tid; i < 448; i += 128)
        reinterpret_cast<float*>(smem + LUT_OFF)[i] = lut[i];

    // ---- stage A: 358 rows x 256B (pitch 272), 3 commit groups by kh range ----
    const char* abase = reinterpret_cast<const char*>(g_scratch) +
                        ((size_t)imgrow0 + g0) * 256;
    {
        for (int i = tid; i < 130 * 16; i += 128) {
            const int r = i >> 4, c = i & 15;
            cp16(sb + A_OFF + r * APITCH + c * 16, abase + (size_t)r * 256 + c * 16);
        }
        CP_COMMIT();
        for (int i = 130 * 16 + tid; i < 244 * 16; i += 128) {
            const int r = i >> 4, c = i & 15;
            cp16(sb + A_OFF + r * APITCH + c * 16, abase + (size_t)r * 256 + c * 16);
        }
        CP_COMMIT();
        for (int i = 244 * 16 + tid; i < 358 * 16; i += 128) {
            const int r = i >> 4, c = i & 15;
            cp16(sb + A_OFF + r * APITCH + c * 16, abase + (size_t)r * 256 + c * 16);
        }
        CP_COMMIT();
    }

    // ---- MMA mainloop ----
    float acc[2][8][4];
    #pragma unroll
    for (int mt = 0; mt < 2; ++mt)
        #pragma unroll
        for (int nt = 0; nt < 8; ++nt)
            #pragma unroll
            for (int i = 0; i < 4; ++i) acc[mt][nt][i] = 0.f;

    const int laneR = lane & 15;
    const int blk   = lane >> 4;        // 0/1 -> k 0-7 / 8-15 halves

    #pragma unroll
    for (int kh = 0; kh < 3; ++kh) {
        if (kh == 0)      asm volatile("cp.async.wait_group 2;" ::: "memory");
        else if (kh == 1) asm volatile("cp.async.wait_group 1;" ::: "memory");
        else              asm volatile("cp.async.wait_group 0;" ::: "memory");
        __syncthreads();

        #pragma unroll
        for (int kw = 0; kw < 3; ++kw) {
            const int tap = kh * 3 + kw;
            const int rowbase = warp * 32 + kh * 114 + kw + laneR;
            const u32 a0addr = sb + A_OFF + rowbase * APITCH + blk * 16;
            const char* bcol = smem + B_OFF + tap * BTAP +
                               (lane >> 2) * BPITCH + (2 * (lane & 3)) * 2;
            #pragma unroll
            for (int kt = 0; kt < 4; ++kt) {
                u32 A0[4], A1[4], A2[4], A3[4];
                const u32 ka = a0addr + kt * 32;
                ldm4(A0, ka);                       // mt0 split0
                ldm4(A1, ka + 16 * APITCH);         // mt1 split0
                ldm4(A2, ka + 128);                 // mt0 split1
                ldm4(A3, ka + 16 * APITCH + 128);   // mt1 split1
                const char* bk = bcol + kt * 32;
                #pragma unroll
                for (int nt = 0; nt < 8; ++nt) {
                    const u32 b0 = *reinterpret_cast<const u32*>(bk + nt * 8 * BPITCH);
                    const u32 b1 = *reinterpret_cast<const u32*>(bk + nt * 8 * BPITCH + 16);
                    mma16816(acc[0][nt], A0, b0, b1);
                    mma16816(acc[1][nt], A1, b0, b1);
                    mma16816(acc[0][nt], A2, b0, b1);   // same B: weights shared by splits
                    mma16816(acc[1][nt], A3, b0, b1);
                }
            }
        }
    }

    // ---- epilogue: accum -> smem [px][65], LUT bucketize, store ----
    __syncthreads();
    float* sum = reinterpret_cast<float*>(smem);
    #pragma unroll
    for (int mt = 0; mt < 2; ++mt)
        #pragma unroll
        for (int nt = 0; nt < 8; ++nt)
            #pragma unroll
            for (int i = 0; i < 4; ++i) {
                const int row = warp * 32 + mt * 16 + (lane >> 2) + ((i >> 1) << 3);
                const int col = nt * 8 + ((lane & 3) << 1) + (i & 1);
                sum[row * 65 + col] = acc[mt][nt][i];
            }
    __syncthreads();

    const int j = tid;
    const int s = s0 + j;
    const int rimg = s / 114 - 1;
    const int c = s - (rimg + 1) * 114;
    if (c < 112 && rimg < 112) {
        const int q = rimg * 112 + c;
        float* op = out + (size_t)n * 64 * 12544 + q;
        const float* sl = reinterpret_cast<const float*>(smem + LUT_OFF);
        #pragma unroll 4
        for (int co = 0; co < 64; ++co) {
            const float v = sum[j * 65 + co];
            const float* tt = sl + co * 7;
            const float t0 = tt[0], t1 = tt[1], t2 = tt[2], t3 = tt[3],
                        t4 = tt[4], t5 = tt[5], t6 = tt[6];
            float r = v;
            if (v <= t0)            r = 0.f;
            if (v > t0 && v < t1)   r = 1.f;
            if (v >= t1 && v <= t2) r = 2.f;
            if (v > t2 && v < t3)   r = 3.f;
            if (v >= t3 && v <= t4) r = 4.f;
            if (v > t4 && v < t5)   r = 5.f;
            if (v >= t5 && v <= t6) r = 6.f;
            if (v > t6)             r = 7.f;
            op[(size_t)co * 12544] = r;
        }
    }
}

// ---------------------------------------------------------------------------
extern "C" void kernel_launch(void* const* d_in, const int* in_sizes, int n_in,
                              void* d_out, int out_size) {
    (void)in_sizes; (void)n_in; (void)out_size;
    const float* x   = (const float*)d_in[0];
    const float* w   = (const float*)d_in[1];
    const float* lut = (const float*)d_in[2];
    float* out = (float*)d_out;

    cudaFuncSetAttribute(conv_mma_kernel,
                         cudaFuncAttributeMaxDynamicSharedMemorySize, SMEM_TOTAL);

    binarize_kernel<<<64, 576>>>(w);
    pad_zero_kernel<<<32, 256>>>();
    convert_kernel<<<dim3(392, 32), 256>>>(x);
    conv_mma_kernel<<<dim3(100, 32), 128, SMEM_TOTAL>>>(lut, out);
}

// round 4
// speedup vs baseline: 3.1915x; 1.1380x over previous
#include <cuda_runtime.h>
#include <cuda_bf16.h>
#include <cstdint>

typedef unsigned long long ull;
typedef uint32_t u32;

#define ROWS_IMG 12996          // 114*114 padded pixels per image
#define GUARD    128
#define TAIL     256
#define TOT_ROWS (GUARD + 32 * ROWS_IMG + TAIL)

// scratch: [row][128 bf16] = 256 B/row : split0 (64 ci bf16) | split1 (64 ci bf16)
__device__ __align__(16) __nv_bfloat16 g_scratch[(size_t)TOT_ROWS * 128];
__device__ __align__(16) __nv_bfloat16 g_wbf[9 * 64 * 64];   // [tap][co][ci]

// ---------------- helpers ----------------
__device__ __forceinline__ u32 smem_u32(const void* p) {
    u32 a;
    asm("{ .reg .u64 t; cvta.to.shared.u64 t, %1; cvt.u32.u64 %0, t; }" : "=r"(a) : "l"(p));
    return a;
}
__device__ __forceinline__ void cp16(u32 dst, const void* src) {
    asm volatile("cp.async.cg.shared.global [%0], [%1], 16;" :: "r"(dst), "l"(src));
}
#define CP_COMMIT() asm volatile("cp.async.commit_group;" ::: "memory")

__device__ __forceinline__ void ldm4(u32* r, u32 addr) {
    asm volatile("ldmatrix.sync.aligned.m8n8.x4.shared.b16 {%0,%1,%2,%3}, [%4];"
                 : "=r"(r[0]), "=r"(r[1]), "=r"(r[2]), "=r"(r[3]) : "r"(addr));
}
__device__ __forceinline__ void mma16816(float* c, const u32* a, u32 b0, u32 b1) {
    asm volatile(
        "mma.sync.aligned.m16n8k16.row.col.f32.bf16.bf16.f32 "
        "{%0,%1,%2,%3}, {%4,%5,%6,%7}, {%8,%9}, {%0,%1,%2,%3};"
        : "+f"(c[0]), "+f"(c[1]), "+f"(c[2]), "+f"(c[3])
        : "r"(a[0]), "r"(a[1]), "r"(a[2]), "r"(a[3]), "r"(b0), "r"(b1));
}

// ---------------------------------------------------------------------------
// Kernel 1: binarize weights -> bf16, layout [tap][co][ci]
// ---------------------------------------------------------------------------
__global__ void binarize_kernel(const float* __restrict__ w) {
    __shared__ float rb[18], rb2[18], rb3[18];
    __shared__ float s_mean, s_scale;
    const int co = blockIdx.x;
    const int e = threadIdx.x;           // e = ci*9 + tap
    const int lane = e & 31, wid = e >> 5;
    const float v = w[co * 576 + e];

    float s = v;
    #pragma unroll
    for (int o = 16; o > 0; o >>= 1) s += __shfl_down_sync(0xffffffffu, s, o);
    if (lane == 0) rb[wid] = s;
    __syncthreads();
    if (e == 0) {
        float t = 0.f;
        for (int i = 0; i < 18; ++i) t += rb[i];
        s_mean = t * (1.0f / 576.0f);
    }
    __syncthreads();
    const float d = v - s_mean;
    float sq = d * d, ab = fabsf(d);
    #pragma unroll
    for (int o = 16; o > 0; o >>= 1) {
        sq += __shfl_down_sync(0xffffffffu, sq, o);
        ab += __shfl_down_sync(0xffffffffu, ab, o);
    }
    if (lane == 0) { rb2[wid] = sq; rb3[wid] = ab; }
    __syncthreads();
    if (e == 0) {
        float t2 = 0.f, t3 = 0.f;
        for (int i = 0; i < 18; ++i) { t2 += rb2[i]; t3 += rb3[i]; }
        const float stdv = sqrtf(t2 / 575.0f);
        const float mean_abs = t3 / (576.0f * stdv);
        s_scale = exp2f(rintf(log2f(mean_abs)));
    }
    __syncthreads();
    const float bv = (d > 0.f) ? s_scale : ((d < 0.f) ? -s_scale : 0.f);
    const int tap = e % 9, ci = e / 9;
    g_wbf[(tap * 64 + co) * 64 + ci] = __float2bfloat16(bv);
}

// ---------------------------------------------------------------------------
// Kernel 2: zero padding regions of scratch (incl. head guard + tail)
// ---------------------------------------------------------------------------
__global__ void pad_zero_kernel() {
    uint4* base = reinterpret_cast<uint4*>(g_scratch);   // 16 uint4 per row
    const uint4 z = make_uint4(0, 0, 0, 0);
    if (blockIdx.x == 32) {      // head guard + tail
        for (int i = threadIdx.x; i < GUARD * 16; i += blockDim.x) base[i] = z;
        uint4* tail = base + ((size_t)GUARD + 32 * (size_t)ROWS_IMG) * 16;
        for (int i = threadIdx.x; i < TAIL * 16; i += blockDim.x) tail[i] = z;
        return;
    }
    const int n = blockIdx.x;
    const size_t imgrow0 = GUARD + (size_t)n * ROWS_IMG;
    // padded rows r'=0 (img row -1) and r'=113 (img row 112): 114 rows each
    for (int i = threadIdx.x; i < 228 * 16; i += blockDim.x) {
        const int r = i >> 4, c = i & 15;
        const size_t row = imgrow0 + (r < 114 ? r : (12882 - 114 + r));
        base[row * 16 + c] = z;
    }
    // pad cols 112,113 for padded rows r'=1..112
    for (int i = threadIdx.x; i < 112 * 2 * 16; i += blockDim.x) {
        const int rp  = 1 + (i >> 5);
        const int col = 112 + ((i >> 4) & 1);
        const int c   = i & 15;
        base[(imgrow0 + (size_t)rp * 114 + col) * 16 + c] = z;
    }
}

// ---------------------------------------------------------------------------
// Kernel 3: convert x fp32 [n][ci][q] -> bf16 2-split scratch rows
// ---------------------------------------------------------------------------
__global__ void convert_kernel(const float* __restrict__ x) {
    __shared__ float sm[64][33];
    const int n = blockIdx.y;
    const int q0 = blockIdx.x * 32;
    const int t = threadIdx.x;
    const int w8 = t >> 5, l = t & 31;
    #pragma unroll
    for (int r = 0; r < 8; ++r) {
        const int ci = w8 * 8 + r;
        sm[ci][l] = x[((size_t)n * 64 + ci) * 12544 + q0 + l];
    }
    __syncthreads();
    const int pix = t >> 3, g = t & 7;
    const int q = q0 + pix;
    const int r = q / 112, c = q - r * 112;
    const size_t row = GUARD + (size_t)n * ROWS_IMG + (size_t)(r + 1) * 114 + c;
    __nv_bfloat16* dst = g_scratch + row * 128 + g * 8;
    __nv_bfloat16 hi[8], lo[8];
    #pragma unroll
    for (int i = 0; i < 8; ++i) {
        const float f = sm[g * 8 + i][pix];
        hi[i] = __float2bfloat16(f);
        const float r1 = f - __bfloat162float(hi[i]);
        lo[i] = __float2bfloat16(r1);
    }
    *reinterpret_cast<uint4*>(dst)      = *reinterpret_cast<uint4*>(hi);
    *reinterpret_cast<uint4*>(dst + 64) = *reinterpret_cast<uint4*>(lo);
}

// ---------------------------------------------------------------------------
// Kernel 4: implicit-GEMM conv via mma.sync m16n8k16 bf16 + LUT bucketize
// Block: 256 threads (8 warps), tile M=256 px x N=64 co.
// ---------------------------------------------------------------------------
#define AROWS  486                       // 256 + 2*114 + 2
#define APITCH 272
#define A_OFF  0
#define B_OFF  132224                    // 486*272 = 132192, pad to 128
#define BPITCH 144
#define BTAP   (64 * 144)                // 9216
#define LUT_OFF (B_OFF + 9 * BTAP)       // 215168
#define SMEM_TOTAL (LUT_OFF + 1792 + 64) // 217024

__global__ void __launch_bounds__(256, 1)
conv_mma_kernel(const float* __restrict__ lut, float* __restrict__ out) {
    extern __shared__ __align__(1024) char smem[];
    const u32 sb = smem_u32(smem);
    const int tid = threadIdx.x, warp = tid >> 5, lane = tid & 31;
    const int tile = blockIdx.x, n = blockIdx.y;
    const int s0 = 114 + tile * 256;
    const size_t imgrow0 = GUARD + (size_t)n * ROWS_IMG;
    const long g0 = (long)s0 - 115;      // first staged (image-local) row

    // ---- stage B (9 taps, 64co x 64ci -> 144B pitch, conflict-free) ----
    {
        const char* wsrc = reinterpret_cast<const char*>(g_wbf);
        for (int i = tid; i < 9 * 64 * 8; i += 256) {
            const int tap = i >> 9, r = (i >> 3) & 63, c = i & 7;
            cp16(sb + B_OFF + tap * BTAP + r * BPITCH + c * 16,
                 wsrc + ((size_t)(tap * 64 + r) * 64 + c * 8) * 2);
        }
    }
    for (int i = tid; i < 448; i += 256)
        reinterpret_cast<float*>(smem + LUT_OFF)[i] = lut[i];

    // ---- stage A: 486 rows x 256B (pitch 272), 3 commit groups by kh ----
    const char* abase = reinterpret_cast<const char*>(g_scratch) +
                        ((size_t)imgrow0 + g0) * 256;
    {
        for (int i = tid; i < 258 * 16; i += 256) {
            const int r = i >> 4, c = i & 15;
            cp16(sb + A_OFF + r * APITCH + c * 16, abase + (size_t)r * 256 + c * 16);
        }
        CP_COMMIT();
        for (int i = 258 * 16 + tid; i < 372 * 16; i += 256) {
            const int r = i >> 4, c = i & 15;
            cp16(sb + A_OFF + r * APITCH + c * 16, abase + (size_t)r * 256 + c * 16);
        }
        CP_COMMIT();
        for (int i = 372 * 16 + tid; i < 486 * 16; i += 256) {
            const int r = i >> 4, c = i & 15;
            cp16(sb + A_OFF + r * APITCH + c * 16, abase + (size_t)r * 256 + c * 16);
        }
        CP_COMMIT();
    }

    // ---- MMA mainloop ----
    float acc[2][8][4];
    #pragma unroll
    for (int mt = 0; mt < 2; ++mt)
        #pragma unroll
        for (int nt = 0; nt < 8; ++nt)
            #pragma unroll
            for (int i = 0; i < 4; ++i) acc[mt][nt][i] = 0.f;

    const int laneR = lane & 15;
    const int blk   = lane >> 4;         // 0/1 -> k 0-7 / 8-15 halves

    #pragma unroll
    for (int kh = 0; kh < 3; ++kh) {
        if (kh == 0)      asm volatile("cp.async.wait_group 2;" ::: "memory");
        else if (kh == 1) asm volatile("cp.async.wait_group 1;" ::: "memory");
        else              asm volatile("cp.async.wait_group 0;" ::: "memory");
        __syncthreads();

        #pragma unroll
        for (int kw = 0; kw < 3; ++kw) {
            const int tap = kh * 3 + kw;
            const int rowbase = warp * 32 + kh * 114 + kw + laneR;
            const u32 a0addr = sb + A_OFF + rowbase * APITCH + blk * 16;
            const char* bcol = smem + B_OFF + tap * BTAP +
                               (lane >> 2) * BPITCH + (2 * (lane & 3)) * 2;
            #pragma unroll
            for (int kt = 0; kt < 4; ++kt) {
                u32 A0[4], A1[4], A2[4], A3[4];
                const u32 ka = a0addr + kt * 32;
                ldm4(A0, ka);                       // mt0 split0
                ldm4(A1, ka + 16 * APITCH);         // mt1 split0
                ldm4(A2, ka + 128);                 // mt0 split1
                ldm4(A3, ka + 16 * APITCH + 128);   // mt1 split1
                const char* bk = bcol + kt * 32;
                #pragma unroll
                for (int nt = 0; nt < 8; ++nt) {
                    const u32 b0 = *reinterpret_cast<const u32*>(bk + nt * 8 * BPITCH);
                    const u32 b1 = *reinterpret_cast<const u32*>(bk + nt * 8 * BPITCH + 16);
                    mma16816(acc[0][nt], A0, b0, b1);
                    mma16816(acc[1][nt], A1, b0, b1);
                    mma16816(acc[0][nt], A2, b0, b1);   // same B: splits share weights
                    mma16816(acc[1][nt], A3, b0, b1);
                }
            }
        }
    }

    // ---- epilogue: accum -> smem [px][65], LUT bucketize, store ----
    __syncthreads();
    float* sum = reinterpret_cast<float*>(smem);
    #pragma unroll
    for (int mt = 0; mt < 2; ++mt)
        #pragma unroll
        for (int nt = 0; nt < 8; ++nt)
            #pragma unroll
            for (int i = 0; i < 4; ++i) {
                const int row = warp * 32 + mt * 16 + (lane >> 2) + ((i >> 1) << 3);
                const int col = nt * 8 + ((lane & 3) << 1) + (i & 1);
                sum[row * 65 + col] = acc[mt][nt][i];
            }
    __syncthreads();

    const int j = tid;
    const int s = s0 + j;
    const int rimg = s / 114 - 1;
    const int c = s - (rimg + 1) * 114;
    if (c < 112 && rimg < 112) {
        const int q = rimg * 112 + c;
        float* op = out + (size_t)n * 64 * 12544 + q;
        const float* sl = reinterpret_cast<const float*>(smem + LUT_OFF);
        #pragma unroll 4
        for (int co = 0; co < 64; ++co) {
            const float v = sum[j * 65 + co];
            const float* tt = sl + co * 7;
            const float t0 = tt[0], t1 = tt[1], t2 = tt[2], t3 = tt[3],
                        t4 = tt[4], t5 = tt[5], t6 = tt[6];
            float r = v;
            if (v <= t0)            r = 0.f;
            if (v > t0 && v < t1)   r = 1.f;
            if (v >= t1 && v <= t2) r = 2.f;
            if (v > t2 && v < t3)   r = 3.f;
            if (v >= t3 && v <= t4) r = 4.f;
            if (v > t4 && v < t5)   r = 5.f;
            if (v >= t5 && v <= t6) r = 6.f;
            if (v > t6)             r = 7.f;
            op[(size_t)co * 12544] = r;
        }
    }
}

// ---------------------------------------------------------------------------
extern "C" void kernel_launch(void* const* d_in, const int* in_sizes, int n_in,
                              void* d_out, int out_size) {
    (void)in_sizes; (void)n_in; (void)out_size;
    const float* x   = (const float*)d_in[0];
    const float* w   = (const float*)d_in[1];
    const float* lut = (const float*)d_in[2];
    float* out = (float*)d_out;

    cudaFuncSetAttribute(conv_mma_kernel,
                         cudaFuncAttributeMaxDynamicSharedMemorySize, SMEM_TOTAL);

    binarize_kernel<<<64, 576>>>(w);
    pad_zero_kernel<<<33, 256>>>();
    convert_kernel<<<dim3(392, 32), 256>>>(x);
    conv_mma_kernel<<<dim3(50, 32), 256, SMEM_TOTAL>>>(lut, out);
}

// round 5
// speedup vs baseline: 3.1948x; 1.0010x over previous
#include <cuda_runtime.h>
#include <cuda_bf16.h>
#include <cstdint>

typedef unsigned long long ull;
typedef uint32_t u32;

#define ROWS_IMG 12996          // 114*114 padded pixels per image
#define GUARD    128
#define TAIL     256
#define TOT_ROWS (GUARD + 32 * ROWS_IMG + TAIL)

// scratch: [row][128 bf16] = 256 B/row : split0 (64 ci bf16) | split1 (64 ci bf16)
__device__ __align__(16) __nv_bfloat16 g_scratch[(size_t)TOT_ROWS * 128];
__device__ __align__(16) __nv_bfloat16 g_wbf[9 * 64 * 64];   // [tap][co][ci]

// ---------------- helpers ----------------
__device__ __forceinline__ u32 smem_u32(const void* p) {
    u32 a;
    asm("{ .reg .u64 t; cvta.to.shared.u64 t, %1; cvt.u32.u64 %0, t; }" : "=r"(a) : "l"(p));
    return a;
}
__device__ __forceinline__ void cp16(u32 dst, const void* src) {
    asm volatile("cp.async.cg.shared.global [%0], [%1], 16;" :: "r"(dst), "l"(src));
}
#define CP_COMMIT() asm volatile("cp.async.commit_group;" ::: "memory")

__device__ __forceinline__ void ldm4(u32* r, u32 addr) {
    asm volatile("ldmatrix.sync.aligned.m8n8.x4.shared.b16 {%0,%1,%2,%3}, [%4];"
                 : "=r"(r[0]), "=r"(r[1]), "=r"(r[2]), "=r"(r[3]) : "r"(addr));
}
__device__ __forceinline__ void mma16816(float* c, const u32* a, u32 b0, u32 b1) {
    asm volatile(
        "mma.sync.aligned.m16n8k16.row.col.f32.bf16.bf16.f32 "
        "{%0,%1,%2,%3}, {%4,%5,%6,%7}, {%8,%9}, {%0,%1,%2,%3};"
        : "+f"(c[0]), "+f"(c[1]), "+f"(c[2]), "+f"(c[3])
        : "r"(a[0]), "r"(a[1]), "r"(a[2]), "r"(a[3]), "r"(b0), "r"(b1));
}

// ---------------------------------------------------------------------------
// Kernel 1: binarize weights -> bf16, layout [tap][co][ci]
// ---------------------------------------------------------------------------
__global__ void binarize_kernel(const float* __restrict__ w) {
    __shared__ float rb[18], rb2[18], rb3[18];
    __shared__ float s_mean, s_scale;
    const int co = blockIdx.x;
    const int e = threadIdx.x;           // e = ci*9 + tap
    const int lane = e & 31, wid = e >> 5;
    const float v = w[co * 576 + e];

    float s = v;
    #pragma unroll
    for (int o = 16; o > 0; o >>= 1) s += __shfl_down_sync(0xffffffffu, s, o);
    if (lane == 0) rb[wid] = s;
    __syncthreads();
    if (e == 0) {
        float t = 0.f;
        for (int i = 0; i < 18; ++i) t += rb[i];
        s_mean = t * (1.0f / 576.0f);
    }
    __syncthreads();
    const float d = v - s_mean;
    float sq = d * d, ab = fabsf(d);
    #pragma unroll
    for (int o = 16; o > 0; o >>= 1) {
        sq += __shfl_down_sync(0xffffffffu, sq, o);
        ab += __shfl_down_sync(0xffffffffu, ab, o);
    }
    if (lane == 0) { rb2[wid] = sq; rb3[wid] = ab; }
    __syncthreads();
    if (e == 0) {
        float t2 = 0.f, t3 = 0.f;
        for (int i = 0; i < 18; ++i) { t2 += rb2[i]; t3 += rb3[i]; }
        const float stdv = sqrtf(t2 / 575.0f);
        const float mean_abs = t3 / (576.0f * stdv);
        s_scale = exp2f(rintf(log2f(mean_abs)));
    }
    __syncthreads();
    const float bv = (d > 0.f) ? s_scale : ((d < 0.f) ? -s_scale : 0.f);
    const int tap = e % 9, ci = e / 9;
    g_wbf[(tap * 64 + co) * 64 + ci] = __float2bfloat16(bv);
}

// ---------------------------------------------------------------------------
// Kernel 2: zero padding regions of scratch (incl. head guard + tail)
// ---------------------------------------------------------------------------
__global__ void pad_zero_kernel() {
    uint4* base = reinterpret_cast<uint4*>(g_scratch);   // 16 uint4 per row
    const uint4 z = make_uint4(0, 0, 0, 0);
    if (blockIdx.x == 32) {      // head guard + tail
        for (int i = threadIdx.x; i < GUARD * 16; i += blockDim.x) base[i] = z;
        uint4* tail = base + ((size_t)GUARD + 32 * (size_t)ROWS_IMG) * 16;
        for (int i = threadIdx.x; i < TAIL * 16; i += blockDim.x) tail[i] = z;
        return;
    }
    const int n = blockIdx.x;
    const size_t imgrow0 = GUARD + (size_t)n * ROWS_IMG;
    for (int i = threadIdx.x; i < 228 * 16; i += blockDim.x) {
        const int r = i >> 4, c = i & 15;
        const size_t row = imgrow0 + (r < 114 ? r : (12882 - 114 + r));
        base[row * 16 + c] = z;
    }
    for (int i = threadIdx.x; i < 112 * 2 * 16; i += blockDim.x) {
        const int rp  = 1 + (i >> 5);
        const int col = 112 + ((i >> 4) & 1);
        const int c   = i & 15;
        base[(imgrow0 + (size_t)rp * 114 + col) * 16 + c] = z;
    }
}

// ---------------------------------------------------------------------------
// Kernel 3: convert x fp32 [n][ci][q] -> bf16 2-split scratch rows
// ---------------------------------------------------------------------------
__global__ void convert_kernel(const float* __restrict__ x) {
    __shared__ float sm[64][33];
    const int n = blockIdx.y;
    const int q0 = blockIdx.x * 32;
    const int t = threadIdx.x;
    const int w8 = t >> 5, l = t & 31;
    #pragma unroll
    for (int r = 0; r < 8; ++r) {
        const int ci = w8 * 8 + r;
        sm[ci][l] = x[((size_t)n * 64 + ci) * 12544 + q0 + l];
    }
    __syncthreads();
    const int pix = t >> 3, g = t & 7;
    const int q = q0 + pix;
    const int r = q / 112, c = q - r * 112;
    const size_t row = GUARD + (size_t)n * ROWS_IMG + (size_t)(r + 1) * 114 + c;
    __nv_bfloat16* dst = g_scratch + row * 128 + g * 8;
    __nv_bfloat16 hi[8], lo[8];
    #pragma unroll
    for (int i = 0; i < 8; ++i) {
        const float f = sm[g * 8 + i][pix];
        hi[i] = __float2bfloat16(f);
        const float r1 = f - __bfloat162float(hi[i]);
        lo[i] = __float2bfloat16(r1);
    }
    *reinterpret_cast<uint4*>(dst)      = *reinterpret_cast<uint4*>(hi);
    *reinterpret_cast<uint4*>(dst + 64) = *reinterpret_cast<uint4*>(lo);
}

// ---------------------------------------------------------------------------
// Kernel 4: implicit-GEMM conv via mma.sync m16n8k16 bf16 + LUT bucketize
// Block: 256 threads (8 warps), tile M=256 px x N=64 co.
// Mainloop: 1-step software pipeline (A frags + B regs double-buffered),
// two-pass accumulator ordering to break HMMA RAW chains.
// ---------------------------------------------------------------------------
#define AROWS  486                       // 256 + 2*114 + 2
#define APITCH 272
#define A_OFF  0
#define B_OFF  132224                    // 486*272 = 132192, pad to 128
#define BPITCH 144
#define BTAP   (64 * 144)                // 9216
#define LUT_OFF (B_OFF + 9 * BTAP)       // 215168
#define SMEM_TOTAL (LUT_OFF + 1792 + 64) // 217024

__global__ void __launch_bounds__(256, 1)
conv_mma_kernel(const float* __restrict__ lut, float* __restrict__ out) {
    extern __shared__ __align__(1024) char smem[];
    const u32 sb = smem_u32(smem);
    const int tid = threadIdx.x, warp = tid >> 5, lane = tid & 31;
    const int tile = blockIdx.x, n = blockIdx.y;
    const int s0 = 114 + tile * 256;
    const size_t imgrow0 = GUARD + (size_t)n * ROWS_IMG;
    const long g0 = (long)s0 - 115;      // first staged (image-local) row

    // ---- stage B (9 taps, 64co x 64ci -> 144B pitch, conflict-free) ----
    {
        const char* wsrc = reinterpret_cast<const char*>(g_wbf);
        for (int i = tid; i < 9 * 64 * 8; i += 256) {
            const int tap = i >> 9, r = (i >> 3) & 63, c = i & 7;
            cp16(sb + B_OFF + tap * BTAP + r * BPITCH + c * 16,
                 wsrc + ((size_t)(tap * 64 + r) * 64 + c * 8) * 2);
        }
    }
    for (int i = tid; i < 448; i += 256)
        reinterpret_cast<float*>(smem + LUT_OFF)[i] = lut[i];

    // ---- stage A: 486 rows x 256B (pitch 272), 3 commit groups by kh ----
    const char* abase = reinterpret_cast<const char*>(g_scratch) +
                        ((size_t)imgrow0 + g0) * 256;
    {
        for (int i = tid; i < 258 * 16; i += 256) {
            const int r = i >> 4, c = i & 15;
            cp16(sb + A_OFF + r * APITCH + c * 16, abase + (size_t)r * 256 + c * 16);
        }
        CP_COMMIT();
        for (int i = 258 * 16 + tid; i < 372 * 16; i += 256) {
            const int r = i >> 4, c = i & 15;
            cp16(sb + A_OFF + r * APITCH + c * 16, abase + (size_t)r * 256 + c * 16);
        }
        CP_COMMIT();
        for (int i = 372 * 16 + tid; i < 486 * 16; i += 256) {
            const int r = i >> 4, c = i & 15;
            cp16(sb + A_OFF + r * APITCH + c * 16, abase + (size_t)r * 256 + c * 16);
        }
        CP_COMMIT();
    }

    // ---- MMA mainloop (pipelined) ----
    float acc[2][8][4];
    #pragma unroll
    for (int mt = 0; mt < 2; ++mt)
        #pragma unroll
        for (int nt = 0; nt < 8; ++nt)
            #pragma unroll
            for (int i = 0; i < 4; ++i) acc[mt][nt][i] = 0.f;

    const int laneR = lane & 15;
    const int blk   = lane >> 4;

    u32 afrag[2][16];
    u32 breg[2][16];
    // per-thread invariant bases
    const u32 arow0 = sb + A_OFF + (warp * 32 + laneR) * APITCH + blk * 16;
    const char* brow0 = smem + B_OFF + (lane >> 2) * BPITCH + (lane & 3) * 4;

    #pragma unroll
    for (int kh = 0; kh < 3; ++kh) {
        if (kh == 0)      asm volatile("cp.async.wait_group 2;" ::: "memory");
        else if (kh == 1) asm volatile("cp.async.wait_group 1;" ::: "memory");
        else              asm volatile("cp.async.wait_group 0;" ::: "memory");
        __syncthreads();

        // prologue load: step 0 (kw=0, kt=0)
        {
            const u32 ka = arow0 + (kh * 114) * APITCH;
            ldm4(&afrag[0][0],  ka);
            ldm4(&afrag[0][4],  ka + 16 * APITCH);
            ldm4(&afrag[0][8],  ka + 128);
            ldm4(&afrag[0][12], ka + 16 * APITCH + 128);
            const char* bk = brow0 + (kh * 3) * BTAP;
            #pragma unroll
            for (int nt = 0; nt < 8; ++nt) {
                breg[0][2 * nt]     = *reinterpret_cast<const u32*>(bk + nt * 8 * BPITCH);
                breg[0][2 * nt + 1] = *reinterpret_cast<const u32*>(bk + nt * 8 * BPITCH + 16);
            }
        }

        #pragma unroll
        for (int s = 0; s < 12; ++s) {
            const int cur = s & 1, nxt = cur ^ 1;
            if (s < 11) {
                const int kw = (s + 1) >> 2, kt = (s + 1) & 3;
                const u32 ka = arow0 + (kh * 114 + kw) * APITCH + kt * 32;
                ldm4(&afrag[nxt][0],  ka);
                ldm4(&afrag[nxt][4],  ka + 16 * APITCH);
                ldm4(&afrag[nxt][8],  ka + 128);
                ldm4(&afrag[nxt][12], ka + 16 * APITCH + 128);
                const char* bk = brow0 + (kh * 3 + kw) * BTAP + kt * 32;
                #pragma unroll
                for (int nt = 0; nt < 8; ++nt) {
                    breg[nxt][2 * nt]     = *reinterpret_cast<const u32*>(bk + nt * 8 * BPITCH);
                    breg[nxt][2 * nt + 1] = *reinterpret_cast<const u32*>(bk + nt * 8 * BPITCH + 16);
                }
            }
            // pass 0: split0 (A frags 0/4) — 16 independent HMMAs
            #pragma unroll
            for (int nt = 0; nt < 8; ++nt) {
                mma16816(acc[0][nt], &afrag[cur][0], breg[cur][2 * nt], breg[cur][2 * nt + 1]);
                mma16816(acc[1][nt], &afrag[cur][4], breg[cur][2 * nt], breg[cur][2 * nt + 1]);
            }
            // pass 1: split1 (A frags 8/12)
            #pragma unroll
            for (int nt = 0; nt < 8; ++nt) {
                mma16816(acc[0][nt], &afrag[cur][8],  breg[cur][2 * nt], breg[cur][2 * nt + 1]);
                mma16816(acc[1][nt], &afrag[cur][12], breg[cur][2 * nt], breg[cur][2 * nt + 1]);
            }
        }
    }

    // ---- epilogue: accum -> smem [px][65], LUT bucketize, store ----
    __syncthreads();
    float* sum = reinterpret_cast<float*>(smem);
    #pragma unroll
    for (int mt = 0; mt < 2; ++mt)
        #pragma unroll
        for (int nt = 0; nt < 8; ++nt)
            #pragma unroll
            for (int i = 0; i < 4; ++i) {
                const int row = warp * 32 + mt * 16 + (lane >> 2) + ((i >> 1) << 3);
                const int col = nt * 8 + ((lane & 3) << 1) + (i & 1);
                sum[row * 65 + col] = acc[mt][nt][i];
            }
    __syncthreads();

    const int j = tid;
    const int s = s0 + j;
    const int rimg = s / 114 - 1;
    const int c = s - (rimg + 1) * 114;
    if (c < 112 && rimg < 112) {
        const int q = rimg * 112 + c;
        float* op = out + (size_t)n * 64 * 12544 + q;
        const float* sl = reinterpret_cast<const float*>(smem + LUT_OFF);
        #pragma unroll 4
        for (int co = 0; co < 64; ++co) {
            const float v = sum[j * 65 + co];
            const float* tt = sl + co * 7;
            const float t0 = tt[0], t1 = tt[1], t2 = tt[2], t3 = tt[3],
                        t4 = tt[4], t5 = tt[5], t6 = tt[6];
            float r = v;
            if (v <= t0)            r = 0.f;
            if (v > t0 && v < t1)   r = 1.f;
            if (v >= t1 && v <= t2) r = 2.f;
            if (v > t2 && v < t3)   r = 3.f;
            if (v >= t3 && v <= t4) r = 4.f;
            if (v > t4 && v < t5)   r = 5.f;
            if (v >= t5 && v <= t6) r = 6.f;
            if (v > t6)             r = 7.f;
            op[(size_t)co * 12544] = r;
        }
    }
}

// ---------------------------------------------------------------------------
extern "C" void kernel_launch(void* const* d_in, const int* in_sizes, int n_in,
                              void* d_out, int out_size) {
    (void)in_sizes; (void)n_in; (void)out_size;
    const float* x   = (const float*)d_in[0];
    const float* w   = (const float*)d_in[1];
    const float* lut = (const float*)d_in[2];
    float* out = (float*)d_out;

    cudaFuncSetAttribute(conv_mma_kernel,
                         cudaFuncAttributeMaxDynamicSharedMemorySize, SMEM_TOTAL);

    binarize_kernel<<<64, 576>>>(w);
    pad_zero_kernel<<<33, 256>>>();
    convert_kernel<<<dim3(392, 32), 256>>>(x);
    conv_mma_kernel<<<dim3(50, 32), 256, SMEM_TOTAL>>>(lut, out);
}

// round 6
// speedup vs baseline: 3.1985x; 1.0012x over previous
#include <cuda_runtime.h>
#include <cuda_bf16.h>
#include <cstdint>

typedef unsigned long long ull;
typedef uint32_t u32;

#define ROWS_IMG 12996          // 114*114 padded pixels per image
#define GUARD    128
#define TAIL     256
#define TOT_ROWS (GUARD + 32 * ROWS_IMG + TAIL)

// scratch: [row][128 bf16] = 256 B/row : split0 (64 ci bf16) | split1 (64 ci bf16)
__device__ __align__(16) __nv_bfloat16 g_scratch[(size_t)TOT_ROWS * 128];
__device__ __align__(16) __nv_bfloat16 g_wbf[9 * 64 * 64];   // [tap][co][ci]

// ---------------- helpers ----------------
__device__ __forceinline__ u32 smem_u32(const void* p) {
    u32 a;
    asm("{ .reg .u64 t; cvta.to.shared.u64 t, %1; cvt.u32.u64 %0, t; }" : "=r"(a) : "l"(p));
    return a;
}
__device__ __forceinline__ void cp16(u32 dst, const void* src) {
    asm volatile("cp.async.cg.shared.global [%0], [%1], 16;" :: "r"(dst), "l"(src));
}
#define CP_COMMIT() asm volatile("cp.async.commit_group;" ::: "memory")

__device__ __forceinline__ void ldm4(u32* r, u32 addr) {
    asm volatile("ldmatrix.sync.aligned.m8n8.x4.shared.b16 {%0,%1,%2,%3}, [%4];"
                 : "=r"(r[0]), "=r"(r[1]), "=r"(r[2]), "=r"(r[3]) : "r"(addr));
}
__device__ __forceinline__ void mma16816(float* c, const u32* a, u32 b0, u32 b1) {
    asm volatile(
        "mma.sync.aligned.m16n8k16.row.col.f32.bf16.bf16.f32 "
        "{%0,%1,%2,%3}, {%4,%5,%6,%7}, {%8,%9}, {%0,%1,%2,%3};"
        : "+f"(c[0]), "+f"(c[1]), "+f"(c[2]), "+f"(c[3])
        : "r"(a[0]), "r"(a[1]), "r"(a[2]), "r"(a[3]), "r"(b0), "r"(b1));
}

// ---------------------------------------------------------------------------
// Kernel 1: binarize weights -> bf16, layout [tap][co][ci]
// ---------------------------------------------------------------------------
__global__ void binarize_kernel(const float* __restrict__ w) {
    __shared__ float rb[18], rb2[18], rb3[18];
    __shared__ float s_mean, s_scale;
    const int co = blockIdx.x;
    const int e = threadIdx.x;           // e = ci*9 + tap
    const int lane = e & 31, wid = e >> 5;
    const float v = w[co * 576 + e];

    float s = v;
    #pragma unroll
    for (int o = 16; o > 0; o >>= 1) s += __shfl_down_sync(0xffffffffu, s, o);
    if (lane == 0) rb[wid] = s;
    __syncthreads();
    if (e == 0) {
        float t = 0.f;
        for (int i = 0; i < 18; ++i) t += rb[i];
        s_mean = t * (1.0f / 576.0f);
    }
    __syncthreads();
    const float d = v - s_mean;
    float sq = d * d, ab = fabsf(d);
    #pragma unroll
    for (int o = 16; o > 0; o >>= 1) {
        sq += __shfl_down_sync(0xffffffffu, sq, o);
        ab += __shfl_down_sync(0xffffffffu, ab, o);
    }
    if (lane == 0) { rb2[wid] = sq; rb3[wid] = ab; }
    __syncthreads();
    if (e == 0) {
        float t2 = 0.f, t3 = 0.f;
        for (int i = 0; i < 18; ++i) { t2 += rb2[i]; t3 += rb3[i]; }
        const float stdv = sqrtf(t2 / 575.0f);
        const float mean_abs = t3 / (576.0f * stdv);
        s_scale = exp2f(rintf(log2f(mean_abs)));
    }
    __syncthreads();
    const float bv = (d > 0.f) ? s_scale : ((d < 0.f) ? -s_scale : 0.f);
    const int tap = e % 9, ci = e / 9;
    g_wbf[(tap * 64 + co) * 64 + ci] = __float2bfloat16(bv);
}

// ---------------------------------------------------------------------------
// Kernel 2: zero padding regions of scratch (incl. head guard + tail)
// ---------------------------------------------------------------------------
__global__ void pad_zero_kernel() {
    uint4* base = reinterpret_cast<uint4*>(g_scratch);   // 16 uint4 per row
    const uint4 z = make_uint4(0, 0, 0, 0);
    if (blockIdx.x == 32) {      // head guard + tail
        for (int i = threadIdx.x; i < GUARD * 16; i += blockDim.x) base[i] = z;
        uint4* tail = base + ((size_t)GUARD + 32 * (size_t)ROWS_IMG) * 16;
        for (int i = threadIdx.x; i < TAIL * 16; i += blockDim.x) tail[i] = z;
        return;
    }
    const int n = blockIdx.x;
    const size_t imgrow0 = GUARD + (size_t)n * ROWS_IMG;
    for (int i = threadIdx.x; i < 228 * 16; i += blockDim.x) {
        const int r = i >> 4, c = i & 15;
        const size_t row = imgrow0 + (r < 114 ? r : (12882 - 114 + r));
        base[row * 16 + c] = z;
    }
    for (int i = threadIdx.x; i < 112 * 2 * 16; i += blockDim.x) {
        const int rp  = 1 + (i >> 5);
        const int col = 112 + ((i >> 4) & 1);
        const int c   = i & 15;
        base[(imgrow0 + (size_t)rp * 114 + col) * 16 + c] = z;
    }
}

// ---------------------------------------------------------------------------
// Kernel 3: convert x fp32 [n][ci][q] -> bf16 2-split scratch rows
// ---------------------------------------------------------------------------
__global__ void convert_kernel(const float* __restrict__ x) {
    __shared__ float sm[64][33];
    const int n = blockIdx.y;
    const int q0 = blockIdx.x * 32;
    const int t = threadIdx.x;
    const int w8 = t >> 5, l = t & 31;
    #pragma unroll
    for (int r = 0; r < 8; ++r) {
        const int ci = w8 * 8 + r;
        sm[ci][l] = x[((size_t)n * 64 + ci) * 12544 + q0 + l];
    }
    __syncthreads();
    const int pix = t >> 3, g = t & 7;
    const int q = q0 + pix;
    const int r = q / 112, c = q - r * 112;
    const size_t row = GUARD + (size_t)n * ROWS_IMG + (size_t)(r + 1) * 114 + c;
    __nv_bfloat16* dst = g_scratch + row * 128 + g * 8;
    __nv_bfloat16 hi[8], lo[8];
    #pragma unroll
    for (int i = 0; i < 8; ++i) {
        const float f = sm[g * 8 + i][pix];
        hi[i] = __float2bfloat16(f);
        const float r1 = f - __bfloat162float(hi[i]);
        lo[i] = __float2bfloat16(r1);
    }
    *reinterpret_cast<uint4*>(dst)      = *reinterpret_cast<uint4*>(hi);
    *reinterpret_cast<uint4*>(dst + 64) = *reinterpret_cast<uint4*>(lo);
}

// ---------------------------------------------------------------------------
// Kernel 4: implicit-GEMM conv via mma.sync m16n8k16 bf16 + LUT bucketize
// Block: 512 threads (16 warps, 4/SMSP), tile M=256 px x N=64 co.
// Each warp owns 16 pixel rows; 36 k-steps (3kh x 3kw x 4kt) x 16 HMMA.
// ---------------------------------------------------------------------------
#define AROWS  486                       // 256 + 2*114 + 2
#define APITCH 272
#define A_OFF  0
#define B_OFF  132224                    // 486*272 = 132192, pad to 128
#define BPITCH 144
#define BTAP   (64 * 144)                // 9216
#define LUT_OFF (B_OFF + 9 * BTAP)       // 215168
#define SMEM_TOTAL (LUT_OFF + 1792 + 64) // 217024

__global__ void __launch_bounds__(512, 1)
conv_mma_kernel(const float* __restrict__ lut, float* __restrict__ out) {
    extern __shared__ __align__(1024) char smem[];
    const u32 sb = smem_u32(smem);
    const int tid = threadIdx.x, warp = tid >> 5, lane = tid & 31;
    const int tile = blockIdx.x, n = blockIdx.y;
    const int s0 = 114 + tile * 256;
    const size_t imgrow0 = GUARD + (size_t)n * ROWS_IMG;
    const long g0 = (long)s0 - 115;      // first staged (image-local) row

    // ---- stage B (9 taps, 64co x 64ci -> 144B pitch, conflict-free) ----
    {
        const char* wsrc = reinterpret_cast<const char*>(g_wbf);
        for (int i = tid; i < 9 * 64 * 8; i += 512) {
            const int tap = i >> 9, r = (i >> 3) & 63, c = i & 7;
            cp16(sb + B_OFF + tap * BTAP + r * BPITCH + c * 16,
                 wsrc + ((size_t)(tap * 64 + r) * 64 + c * 8) * 2);
        }
    }
    for (int i = tid; i < 448; i += 512)
        reinterpret_cast<float*>(smem + LUT_OFF)[i] = lut[i];

    // ---- stage A: 486 rows x 256B (pitch 272), 3 commit groups by kh ----
    const char* abase = reinterpret_cast<const char*>(g_scratch) +
                        ((size_t)imgrow0 + g0) * 256;
    {
        for (int i = tid; i < 258 * 16; i += 512) {
            const int r = i >> 4, c = i & 15;
            cp16(sb + A_OFF + r * APITCH + c * 16, abase + (size_t)r * 256 + c * 16);
        }
        CP_COMMIT();
        for (int i = 258 * 16 + tid; i < 372 * 16; i += 512) {
            const int r = i >> 4, c = i & 15;
            cp16(sb + A_OFF + r * APITCH + c * 16, abase + (size_t)r * 256 + c * 16);
        }
        CP_COMMIT();
        for (int i = 372 * 16 + tid; i < 486 * 16; i += 512) {
            const int r = i >> 4, c = i & 15;
            cp16(sb + A_OFF + r * APITCH + c * 16, abase + (size_t)r * 256 + c * 16);
        }
        CP_COMMIT();
    }

    // ---- MMA mainloop ----
    float acc[8][4];
    #pragma unroll
    for (int nt = 0; nt < 8; ++nt)
        #pragma unroll
        for (int i = 0; i < 4; ++i) acc[nt][i] = 0.f;

    const int laneR = lane & 15;
    const int blk   = lane >> 4;

    u32 afrag[2][8];                     // [buf][split0(4) | split1(4)]
    u32 breg[2][16];
    const u32 arow0 = sb + A_OFF + (warp * 16 + laneR) * APITCH + blk * 16;
    const char* brow0 = smem + B_OFF + (lane >> 2) * BPITCH + (lane & 3) * 4;

    #pragma unroll
    for (int kh = 0; kh < 3; ++kh) {
        if (kh == 0)      asm volatile("cp.async.wait_group 2;" ::: "memory");
        else if (kh == 1) asm volatile("cp.async.wait_group 1;" ::: "memory");
        else              asm volatile("cp.async.wait_group 0;" ::: "memory");
        __syncthreads();

        // prologue load: step 0 (kw=0, kt=0)
        {
            const u32 ka = arow0 + (kh * 114) * APITCH;
            ldm4(&afrag[0][0], ka);
            ldm4(&afrag[0][4], ka + 128);
            const char* bk = brow0 + (kh * 3) * BTAP;
            #pragma unroll
            for (int nt = 0; nt < 8; ++nt) {
                breg[0][2 * nt]     = *reinterpret_cast<const u32*>(bk + nt * 8 * BPITCH);
                breg[0][2 * nt + 1] = *reinterpret_cast<const u32*>(bk + nt * 8 * BPITCH + 16);
            }
        }

        #pragma unroll
        for (int s = 0; s < 12; ++s) {
            const int cur = s & 1, nxt = cur ^ 1;
            if (s < 11) {
                const int kw = (s + 1) >> 2, kt = (s + 1) & 3;
                const u32 ka = arow0 + (kh * 114 + kw) * APITCH + kt * 32;
                ldm4(&afrag[nxt][0], ka);
                ldm4(&afrag[nxt][4], ka + 128);
                const char* bk = brow0 + (kh * 3 + kw) * BTAP + kt * 32;
                #pragma unroll
                for (int nt = 0; nt < 8; ++nt) {
                    breg[nxt][2 * nt]     = *reinterpret_cast<const u32*>(bk + nt * 8 * BPITCH);
                    breg[nxt][2 * nt + 1] = *reinterpret_cast<const u32*>(bk + nt * 8 * BPITCH + 16);
                }
            }
            // pass 0: split0
            #pragma unroll
            for (int nt = 0; nt < 8; ++nt)
                mma16816(acc[nt], &afrag[cur][0], breg[cur][2 * nt], breg[cur][2 * nt + 1]);
            // pass 1: split1
            #pragma unroll
            for (int nt = 0; nt < 8; ++nt)
                mma16816(acc[nt], &afrag[cur][4], breg[cur][2 * nt], breg[cur][2 * nt + 1]);
        }
    }

    // ---- epilogue: accum -> smem [px][65], LUT bucketize, store ----
    __syncthreads();
    float* sum = reinterpret_cast<float*>(smem);
    #pragma unroll
    for (int nt = 0; nt < 8; ++nt)
        #pragma unroll
        for (int i = 0; i < 4; ++i) {
            const int row = warp * 16 + (lane >> 2) + ((i >> 1) << 3);
            const int col = nt * 8 + ((lane & 3) << 1) + (i & 1);
            sum[row * 65 + col] = acc[nt][i];
        }
    __syncthreads();

    const int j = tid >> 1;              // pixel 0..255
    const int ch = (tid & 1) << 5;       // co half: 0 or 32
    const int s = s0 + j;
    const int rimg = s / 114 - 1;
    const int c = s - (rimg + 1) * 114;
    if (c < 112 && rimg < 112) {
        const int q = rimg * 112 + c;
        float* op = out + (size_t)n * 64 * 12544 + q + (size_t)ch * 12544;
        const float* sl = reinterpret_cast<const float*>(smem + LUT_OFF) + ch * 7;
        const float* sv = sum + j * 65 + ch;
        #pragma unroll 4
        for (int co = 0; co < 32; ++co) {
            const float v = sv[co];
            const float* tt = sl + co * 7;
            const float t0 = tt[0], t1 = tt[1], t2 = tt[2], t3 = tt[3],
                        t4 = tt[4], t5 = tt[5], t6 = tt[6];
            float r = v;
            if (v <= t0)            r = 0.f;
            if (v > t0 && v < t1)   r = 1.f;
            if (v >= t1 && v <= t2) r = 2.f;
            if (v > t2 && v < t3)   r = 3.f;
            if (v >= t3 && v <= t4) r = 4.f;
            if (v > t4 && v < t5)   r = 5.f;
            if (v >= t5 && v <= t6) r = 6.f;
            if (v > t6)             r = 7.f;
            op[(size_t)co * 12544] = r;
        }
    }
}

// ---------------------------------------------------------------------------
extern "C" void kernel_launch(void* const* d_in, const int* in_sizes, int n_in,
                              void* d_out, int out_size) {
    (void)in_sizes; (void)n_in; (void)out_size;
    const float* x   = (const float*)d_in[0];
    const float* w   = (const float*)d_in[1];
    const float* lut = (const float*)d_in[2];
    float* out = (float*)d_out;

    cudaFuncSetAttribute(conv_mma_kernel,
                         cudaFuncAttributeMaxDynamicSharedMemorySize, SMEM_TOTAL);

    binarize_kernel<<<64, 576>>>(w);
    pad_zero_kernel<<<33, 256>>>();
    convert_kernel<<<dim3(392, 32), 256>>>(x);
    conv_mma_kernel<<<dim3(50, 32), 512, SMEM_TOTAL>>>(lut, out);
}